// round 2
// baseline (speedup 1.0000x reference)
#include <cuda_runtime.h>
#include <cstdint>

// ---------------- problem constants ----------------
#define B_SZ   32768
#define DIN    512
#define DOUT   512
#define NLEV   10

// ---------------- GEMM tiling ----------------
#define BM     128
#define BN     128
#define BK     32
#define NKB    (DIN / BK)          // 16 K-blocks
#define STRD   36                  // smem row stride in floats (bank-conflict-free, 144B = 16B aligned)
#define MAX_MT 266                 // sum ceil(count_l/128) <= 256 + 9
#define NT     (DOUT / BN)         // 4 N-tiles
#define STG_F  (BM * STRD)         // floats per stage per operand (4608)
#define SMEM_BYTES (4 * STG_F * 4) // 2 stages x (A+B) = 73728 B

// ---------------- device scratch ----------------
__device__ int g_counts[NLEV];
__device__ int g_offsets[NLEV];
__device__ int g_cursor[NLEV];
__device__ int g_rows[B_SZ];
__device__ int g_is64;
// folded per-level matrices, tf32-rounded, [level][n][k] row-major
__device__ float g_M[NLEV * DOUT * DIN];

// ---------------- PTX helpers (all non-"a"-gated, sm_80+) ----------------
__device__ __forceinline__ uint32_t smem_u32(const void* p) {
    uint32_t a;
    asm("{ .reg .u64 t; cvta.to.shared.u64 t, %1; cvt.u32.u64 %0, t; }" : "=r"(a) : "l"(p));
    return a;
}
__device__ __forceinline__ uint32_t tf32r(float f) {
    uint32_t u;
    asm("cvt.rna.tf32.f32 %0, %1;" : "=r"(u) : "f"(f));
    return u;
}
#define CP16(dst, src) \
    asm volatile("cp.async.cg.shared.global [%0], [%1], 16;" :: "r"(dst), "l"(src))
#define CP_COMMIT() asm volatile("cp.async.commit_group;" ::: "memory")
#define CP_WAIT1()  asm volatile("cp.async.wait_group 1;" ::: "memory")

__device__ __forceinline__ void mma8(float* d, const uint32_t* a, const uint32_t* b) {
    asm volatile(
        "mma.sync.aligned.m16n8k8.row.col.f32.tf32.tf32.f32 "
        "{%0,%1,%2,%3}, {%4,%5,%6,%7}, {%8,%9}, {%0,%1,%2,%3};"
        : "+f"(d[0]), "+f"(d[1]), "+f"(d[2]), "+f"(d[3])
        : "r"(a[0]), "r"(a[1]), "r"(a[2]), "r"(a[3]), "r"(b[0]), "r"(b[1]));
}

// =================================================================
// Kernel 0: detect whether valuations buffer is int64 or int32.
// Reads only first 2KB (safe either way). If data were int32, the
// int64 view mixes two valuations per word -> some value >= 10.
// =================================================================
__global__ void k_detect(const unsigned long long* __restrict__ v) {
    if (threadIdx.x == 0) {
        int ok = 1;
        for (int i = 0; i < 256; i++)
            if (v[i] >= 10ULL) { ok = 0; break; }
        g_is64 = ok;
    }
}

__device__ __forceinline__ int load_val(const void* val, int b) {
    int v = g_is64 ? (int)((const long long*)val)[b] : ((const int*)val)[b];
    return v < 0 ? 0 : (v > 9 ? 9 : v);
}

// =================================================================
// Kernel 1: fold the 10 levels into M[v] = sum_l C[v,l] * W[l]
//   C[v,l] = 0.3*softmax(attn[v])_l*sigmoid(g_l) + [l==v]*0.7*sigmoid(g_v)
// writes tf32-rounded values, natural [v][n][k] layout.
// =================================================================
__global__ void k_fold(const float* __restrict__ W, const float* __restrict__ gates,
                       const float* __restrict__ attn) {
    __shared__ float sC[NLEV][NLEV];
    int tid = threadIdx.x;
    if (tid < NLEV) {
        int v = tid;
        float m = -1e30f;
        for (int l = 0; l < NLEV; l++) m = fmaxf(m, attn[v * NLEV + l]);
        float e[NLEV]; float ssum = 0.f;
        for (int l = 0; l < NLEV; l++) { e[l] = expf(attn[v * NLEV + l] - m); ssum += e[l]; }
        float inv = 1.f / ssum;
        float gv = 1.f / (1.f + expf(-gates[v]));
        for (int l = 0; l < NLEV; l++) {
            float gl = 1.f / (1.f + expf(-gates[l]));
            sC[v][l] = 0.3f * e[l] * inv * gl + ((l == v) ? 0.7f * gv : 0.f);
        }
    }
    __syncthreads();

    int p  = blockIdx.x * blockDim.x + tid;   // 0 .. 65535
    int n  = p >> 7;                          // output feature 0..511
    int k4 = p & 127;                         // float4 index along K

    float4 w[NLEV];
#pragma unroll
    for (int l = 0; l < NLEV; l++)
        w[l] = __ldg((const float4*)(W + ((size_t)l * DOUT + n) * DIN) + k4);

#pragma unroll
    for (int v = 0; v < NLEV; v++) {
        float4 a = make_float4(0.f, 0.f, 0.f, 0.f);
#pragma unroll
        for (int l = 0; l < NLEV; l++) {
            float cc = sC[v][l];
            a.x += cc * w[l].x; a.y += cc * w[l].y;
            a.z += cc * w[l].z; a.w += cc * w[l].w;
        }
        a.x = __uint_as_float(tf32r(a.x)); a.y = __uint_as_float(tf32r(a.y));
        a.z = __uint_as_float(tf32r(a.z)); a.w = __uint_as_float(tf32r(a.w));
        *(float4*)(g_M + ((size_t)v * DOUT + n) * DIN + k4 * 4) = a;
    }
}

// =================================================================
// Kernels 2-5: counting sort of valuations
// =================================================================
__global__ void k_zero() {
    if (threadIdx.x < NLEV) g_counts[threadIdx.x] = 0;
}

__global__ void k_hist(const void* __restrict__ val) {
    __shared__ int sc[NLEV];
    int tid = threadIdx.x;
    if (tid < NLEV) sc[tid] = 0;
    __syncthreads();
    int b = blockIdx.x * 256 + tid;
    atomicAdd(&sc[load_val(val, b)], 1);
    __syncthreads();
    if (tid < NLEV) atomicAdd(&g_counts[tid], sc[tid]);
}

__global__ void k_scan() {
    if (threadIdx.x == 0) {
        int a = 0;
        for (int l = 0; l < NLEV; l++) { g_offsets[l] = a; g_cursor[l] = a; a += g_counts[l]; }
    }
}

__global__ void k_scatter(const void* __restrict__ val) {
    __shared__ int sc[NLEV];
    __shared__ int sbase[NLEV];
    int tid = threadIdx.x;
    if (tid < NLEV) sc[tid] = 0;
    __syncthreads();
    int b = blockIdx.x * 256 + tid;
    int v = load_val(val, b);
    int rank = atomicAdd(&sc[v], 1);
    __syncthreads();
    if (tid < NLEV) sbase[tid] = atomicAdd(&g_cursor[tid], sc[tid]);
    __syncthreads();
    g_rows[sbase[v] + rank] = b;
}

// =================================================================
// Kernel 6: gathered tf32 GEMM  out[row] = M[level] @ x[row] + bias
//   CTA: 128 (gathered M rows) x 128 N, 4 warps of 64x64,
//   mma.sync m16n8k8 tf32, cp.async 2-stage pipeline.
// =================================================================
__global__ void __launch_bounds__(128, 2) padic_gemm(
    const float* __restrict__ x, const float* __restrict__ bias,
    float* __restrict__ out) {
    // ---- tile mapping: which (level, row-tile) is this block? ----
    int mt = blockIdx.x, ntile = blockIdx.y;
    int level = -1, tj = 0, acc = 0;
#pragma unroll
    for (int l = 0; l < NLEV; l++) {
        int c = g_counts[l];
        int tl = (c + BM - 1) >> 7;
        if (level < 0 && mt < acc + tl) { level = l; tj = mt - acc; }
        acc += tl;
    }
    if (level < 0) return;
    int base = g_offsets[level] + tj * BM;
    int cnt  = g_counts[level] - tj * BM;
    if (cnt > BM) cnt = BM;

    extern __shared__ float smem[];
    float* As = smem;                 // [2][BM][STRD]
    float* Bs = smem + 2 * STG_F;     // [2][BN][STRD]
    uint32_t uA = smem_u32(As);
    uint32_t uB = smem_u32(Bs);

    int tid = threadIdx.x, lane = tid & 31, wid = tid >> 5;
    int wm = (wid & 1) * 64;          // warp M origin within tile
    int wn = (wid >> 1) * 64;         // warp N origin within tile

    // per-thread producer row (thread t fills A row t and B row t)
    int r = tid;
    int grow = g_rows[base + (r < cnt ? r : cnt - 1)];
    const float* xrow = x + (size_t)grow * DIN;
    const float* Brow = g_M + ((size_t)level * DOUT + (size_t)(ntile * BN + r)) * DIN;
    uint32_t dA = uA + (uint32_t)r * (STRD * 4);
    uint32_t dB = uB + (uint32_t)r * (STRD * 4);

    float accum[4][8][4];
#pragma unroll
    for (int mf = 0; mf < 4; mf++)
#pragma unroll
        for (int nf = 0; nf < 8; nf++)
#pragma unroll
            for (int q = 0; q < 4; q++) accum[mf][nf][q] = 0.f;

    // ---- prologue: stage 0 ----
    {
        const float4* ga = (const float4*)(xrow);
        const float4* gb = (const float4*)(Brow);
#pragma unroll
        for (int c = 0; c < 8; c++) {
            CP16(dA + c * 16, ga + c);
            CP16(dB + c * 16, gb + c);
        }
        CP_COMMIT();
    }

    // ---- mainloop ----
    for (int kb = 0; kb < NKB; kb++) {
        if (kb + 1 < NKB) {
            int s = (kb + 1) & 1;
            const float4* ga = (const float4*)(xrow + (kb + 1) * BK);
            const float4* gb = (const float4*)(Brow + (kb + 1) * BK);
            uint32_t da = dA + s * (STG_F * 4);
            uint32_t db = dB + s * (STG_F * 4);
#pragma unroll
            for (int c = 0; c < 8; c++) {
                CP16(da + c * 16, ga + c);
                CP16(db + c * 16, gb + c);
            }
        }
        CP_COMMIT();
        CP_WAIT1();
        __syncthreads();

        const float* A = As + (kb & 1) * STG_F;
        const float* B = Bs + (kb & 1) * STG_F;
#pragma unroll
        for (int k8 = 0; k8 < 4; k8++) {
            int kc = k8 * 8 + (lane & 3);
            uint32_t afr[4][4];
            uint32_t bfr[8][2];
#pragma unroll
            for (int mf = 0; mf < 4; mf++) {
                const float* p0 = A + (wm + mf * 16 + (lane >> 2)) * STRD + kc;
                const float* p1 = p0 + 8 * STRD;
                afr[mf][0] = tf32r(p0[0]);
                afr[mf][2] = tf32r(p0[4]);
                afr[mf][1] = tf32r(p1[0]);
                afr[mf][3] = tf32r(p1[4]);
            }
#pragma unroll
            for (int nf = 0; nf < 8; nf++) {
                const float* p = B + (wn + nf * 8 + (lane >> 2)) * STRD + kc;
                bfr[nf][0] = __float_as_uint(p[0]);
                bfr[nf][1] = __float_as_uint(p[4]);
            }
#pragma unroll
            for (int mf = 0; mf < 4; mf++)
#pragma unroll
                for (int nf = 0; nf < 8; nf++)
                    mma8(accum[mf][nf], afr[mf], bfr[nf]);
        }
        __syncthreads();
    }

    // ---- epilogue: add bias, scatter rows back ----
    int colbase = ntile * BN + wn;
#pragma unroll
    for (int mf = 0; mf < 4; mf++) {
        int row0 = wm + mf * 16 + (lane >> 2);
        int row1 = row0 + 8;
        int g0 = g_rows[base + (row0 < cnt ? row0 : cnt - 1)];
        int g1 = g_rows[base + (row1 < cnt ? row1 : cnt - 1)];
        float* o0 = out + (size_t)g0 * DOUT;
        float* o1 = out + (size_t)g1 * DOUT;
        bool v0 = row0 < cnt, v1 = row1 < cnt;
#pragma unroll
        for (int nf = 0; nf < 8; nf++) {
            int col = colbase + nf * 8 + (lane & 3) * 2;
            float2 bb = __ldg((const float2*)(bias + col));
            if (v0) {
                float2 w0;
                w0.x = accum[mf][nf][0] + bb.x;
                w0.y = accum[mf][nf][1] + bb.y;
                *(float2*)(o0 + col) = w0;
            }
            if (v1) {
                float2 w1;
                w1.x = accum[mf][nf][2] + bb.x;
                w1.y = accum[mf][nf][3] + bb.y;
                *(float2*)(o1 + col) = w1;
            }
        }
    }
}

// =================================================================
// kernel_launch
// =================================================================
extern "C" void kernel_launch(void* const* d_in, const int* in_sizes, int n_in,
                              void* d_out, int out_size) {
    const float* x     = (const float*)d_in[0];
    const void*  val   = d_in[1];
    const float* W     = (const float*)d_in[2];
    const float* gates = (const float*)d_in[3];
    const float* attn  = (const float*)d_in[4];
    const float* bias  = (const float*)d_in[5];
    float*       out   = (float*)d_out;

    cudaFuncSetAttribute(padic_gemm, cudaFuncAttributeMaxDynamicSharedMemorySize, SMEM_BYTES);

    k_detect<<<1, 32>>>((const unsigned long long*)val);
    k_fold<<<256, 256>>>(W, gates, attn);
    k_zero<<<1, 32>>>();
    k_hist<<<128, 256>>>(val);
    k_scan<<<1, 32>>>();
    k_scatter<<<128, 256>>>(val);
    padic_gemm<<<dim3(MAX_MT, NT), 128, SMEM_BYTES>>>(x, bias, out);
}

// round 3
// speedup vs baseline: 1.6068x; 1.6068x over previous
#include <cuda_runtime.h>
#include <cuda_fp16.h>
#include <cstdint>

// ---------------- problem constants ----------------
#define B_SZ   32768
#define DIN    512
#define DOUT   512
#define NLEV   10

// ---------------- GEMM tiling ----------------
#define BM     128
#define BN     128
#define BK     32                  // k per stage (fp16) = 64 B per row
#define NKB    (DIN / BK)          // 16 K-blocks
#define NSTG   4                   // cp.async pipeline depth
#define MAX_MT 266                 // sum ceil(count_l/128) <= 256 + 9
#define NT     (DOUT / BN)         // 4 N-tiles
#define STG_B  (BM * 64)           // 8192 B per operand per stage
#define SMEM_BYTES (NSTG * 2 * STG_B)   // 65536

// ---------------- device scratch ----------------
__device__ int g_counts[NLEV];
__device__ int g_offsets[NLEV];
__device__ int g_cursor[NLEV];
__device__ int g_rows[B_SZ];
__device__ int g_is64;
// folded per-level matrices in fp16, [level][n][k]
__device__ __align__(16) __half g_M16[NLEV * DOUT * DIN];
// x pre-gathered into sorted order, fp16, [sorted_row][k]
__device__ __align__(16) __half g_X16[(size_t)B_SZ * DIN];

// ---------------- PTX helpers (all plain sm_80+/75+, no "a"-gated) --------
__device__ __forceinline__ uint32_t smem_u32(const void* p) {
    uint32_t a;
    asm("{ .reg .u64 t; cvta.to.shared.u64 t, %1; cvt.u32.u64 %0, t; }" : "=r"(a) : "l"(p));
    return a;
}
#define CP16(dst, src) \
    asm volatile("cp.async.cg.shared.global [%0], [%1], 16;" :: "r"(dst), "l"(src))
#define CP_COMMIT() asm volatile("cp.async.commit_group;" ::: "memory")
#define CP_WAIT3()  asm volatile("cp.async.wait_group 3;" ::: "memory")

#define LDSM4(r0, r1, r2, r3, addr) \
    asm volatile("ldmatrix.sync.aligned.m8n8.x4.shared.b16 {%0,%1,%2,%3}, [%4];" \
        : "=r"(r0), "=r"(r1), "=r"(r2), "=r"(r3) : "r"(addr))

__device__ __forceinline__ void mma16(float* d, const uint32_t* a, const uint32_t* b) {
    asm volatile(
        "mma.sync.aligned.m16n8k16.row.col.f32.f16.f16.f32 "
        "{%0,%1,%2,%3}, {%4,%5,%6,%7}, {%8,%9}, {%0,%1,%2,%3};"
        : "+f"(d[0]), "+f"(d[1]), "+f"(d[2]), "+f"(d[3])
        : "r"(a[0]), "r"(a[1]), "r"(a[2]), "r"(a[3]), "r"(b[0]), "r"(b[1]));
}

// swizzled byte offset of 16B unit u (0..3) within 64B row `row`
__device__ __forceinline__ uint32_t swz(int row, int u) {
    return (uint32_t)row * 64u + (uint32_t)((u ^ ((row >> 1) & 3)) << 4);
}

// =================================================================
// Kernel 0: detect int64 vs int32 valuations (first 2KB is safe).
// =================================================================
__global__ void k_detect(const unsigned long long* __restrict__ v) {
    if (threadIdx.x == 0) {
        int ok = 1;
        for (int i = 0; i < 256; i++)
            if (v[i] >= 10ULL) { ok = 0; break; }
        g_is64 = ok;
    }
}
__device__ __forceinline__ int load_val(const void* val, int b) {
    int v = g_is64 ? (int)((const long long*)val)[b] : ((const int*)val)[b];
    return v < 0 ? 0 : (v > 9 ? 9 : v);
}

// =================================================================
// Kernel 1: fold 10 levels into M[v] = sum_l C[v,l] * W[l], fp16 out
// =================================================================
__global__ void k_fold(const float* __restrict__ W, const float* __restrict__ gates,
                       const float* __restrict__ attn) {
    __shared__ float sC[NLEV][NLEV];
    int tid = threadIdx.x;
    if (tid < NLEV) {
        int v = tid;
        float m = -1e30f;
        for (int l = 0; l < NLEV; l++) m = fmaxf(m, attn[v * NLEV + l]);
        float e[NLEV]; float ssum = 0.f;
        for (int l = 0; l < NLEV; l++) { e[l] = expf(attn[v * NLEV + l] - m); ssum += e[l]; }
        float inv = 1.f / ssum;
        float gv = 1.f / (1.f + expf(-gates[v]));
        for (int l = 0; l < NLEV; l++) {
            float gl = 1.f / (1.f + expf(-gates[l]));
            sC[v][l] = 0.3f * e[l] * inv * gl + ((l == v) ? 0.7f * gv : 0.f);
        }
    }
    __syncthreads();

    int p  = blockIdx.x * blockDim.x + tid;   // 0 .. 65535
    int n  = p >> 7;                          // output feature 0..511
    int k4 = p & 127;                         // float4 index along K

    float4 w[NLEV];
#pragma unroll
    for (int l = 0; l < NLEV; l++)
        w[l] = __ldg((const float4*)(W + ((size_t)l * DOUT + n) * DIN) + k4);

#pragma unroll
    for (int v = 0; v < NLEV; v++) {
        float4 a = make_float4(0.f, 0.f, 0.f, 0.f);
#pragma unroll
        for (int l = 0; l < NLEV; l++) {
            float cc = sC[v][l];
            a.x += cc * w[l].x; a.y += cc * w[l].y;
            a.z += cc * w[l].z; a.w += cc * w[l].w;
        }
        __half2 h0 = __floats2half2_rn(a.x, a.y);
        __half2 h1 = __floats2half2_rn(a.z, a.w);
        uint2 o;
        o.x = *reinterpret_cast<unsigned*>(&h0);
        o.y = *reinterpret_cast<unsigned*>(&h1);
        *(uint2*)(g_M16 + ((size_t)v * DOUT + n) * DIN + (size_t)k4 * 4) = o;
    }
}

// =================================================================
// Kernels 2-5: counting sort of valuations
// =================================================================
__global__ void k_zero() {
    if (threadIdx.x < NLEV) g_counts[threadIdx.x] = 0;
}
__global__ void k_hist(const void* __restrict__ val) {
    __shared__ int sc[NLEV];
    int tid = threadIdx.x;
    if (tid < NLEV) sc[tid] = 0;
    __syncthreads();
    int b = blockIdx.x * 256 + tid;
    atomicAdd(&sc[load_val(val, b)], 1);
    __syncthreads();
    if (tid < NLEV) atomicAdd(&g_counts[tid], sc[tid]);
}
__global__ void k_scan() {
    if (threadIdx.x == 0) {
        int a = 0;
        for (int l = 0; l < NLEV; l++) { g_offsets[l] = a; g_cursor[l] = a; a += g_counts[l]; }
    }
}
__global__ void k_scatter(const void* __restrict__ val) {
    __shared__ int sc[NLEV];
    __shared__ int sbase[NLEV];
    int tid = threadIdx.x;
    if (tid < NLEV) sc[tid] = 0;
    __syncthreads();
    int b = blockIdx.x * 256 + tid;
    int v = load_val(val, b);
    int rank = atomicAdd(&sc[v], 1);
    __syncthreads();
    if (tid < NLEV) sbase[tid] = atomicAdd(&g_cursor[tid], sc[tid]);
    __syncthreads();
    g_rows[sbase[v] + rank] = b;
}

// =================================================================
// Kernel 6: convert x to fp16 AND pre-gather into sorted row order.
// One block per sorted row, 128 threads x float4.
// =================================================================
__global__ void k_xcvt(const float* __restrict__ x) {
    int row = blockIdx.x;
    int t = threadIdx.x;
    int src = g_rows[row];
    float4 v = __ldg((const float4*)(x + (size_t)src * DIN) + t);
    __half2 h0 = __floats2half2_rn(v.x, v.y);
    __half2 h1 = __floats2half2_rn(v.z, v.w);
    uint2 o;
    o.x = *reinterpret_cast<unsigned*>(&h0);
    o.y = *reinterpret_cast<unsigned*>(&h1);
    ((uint2*)(g_X16 + (size_t)row * DIN))[t] = o;
}

// =================================================================
// Kernel 7: fp16 GEMM  out[g_rows[r]] = M16[level] @ X16[r] + bias
//   CTA 128x128, 4 warps of 64x64, mma.m16n8k16, ldmatrix fragments,
//   4-stage cp.async pipeline.
// =================================================================
__global__ void __launch_bounds__(128, 2) padic_gemm(
    const float* __restrict__ bias, float* __restrict__ out) {
    // ---- tile map ----
    int mt = blockIdx.x, ntile = blockIdx.y;
    int level = -1, tj = 0, acc = 0;
#pragma unroll
    for (int l = 0; l < NLEV; l++) {
        int c = g_counts[l];
        int tl = (c + BM - 1) >> 7;
        if (level < 0 && mt < acc + tl) { level = l; tj = mt - acc; }
        acc += tl;
    }
    if (level < 0) return;
    int base = g_offsets[level] + tj * BM;
    int cnt  = g_counts[level] - tj * BM;
    if (cnt > BM) cnt = BM;

    extern __shared__ char smem[];
    uint32_t sb = smem_u32(smem);
    int tid = threadIdx.x, lane = tid & 31, wid = tid >> 5;
    int wm = (wid & 1) * 64;
    int wn = (wid >> 1) * 64;

    // producer: thread r fills A row r and B row r of each stage (4 x 16B each)
    int r = tid;
    int rowA = base + r; if (rowA > B_SZ - 1) rowA = B_SZ - 1;
    const char* srcA = (const char*)(g_X16 + (size_t)rowA * DIN);
    const char* srcB = (const char*)(g_M16 + ((size_t)level * DOUT + (size_t)(ntile * BN + r)) * DIN);
    uint32_t swzr[4];
#pragma unroll
    for (int u = 0; u < 4; u++) swzr[u] = swz(r, u);

    float accum[4][8][4];
#pragma unroll
    for (int mf = 0; mf < 4; mf++)
#pragma unroll
        for (int nf = 0; nf < 8; nf++)
#pragma unroll
            for (int q = 0; q < 4; q++) accum[mf][nf][q] = 0.f;

    // ---- prologue: stages 0..2 ----
#pragma unroll
    for (int p = 0; p < NSTG - 1; p++) {
        uint32_t sa = sb + p * (2 * STG_B);
        uint32_t sbB = sa + STG_B;
#pragma unroll
        for (int u = 0; u < 4; u++) {
            CP16(sa + swzr[u], srcA + p * 64 + u * 16);
            CP16(sbB + swzr[u], srcB + p * 64 + u * 16);
        }
        CP_COMMIT();
    }

    // precompute LDSM lane addresses (relative to stage base)
    int sub = lane >> 3, rr = lane & 7;
    // A: matrices (m0..7,u0),(m8..15,u0),(m0..7,u0+1),(m8..15,u0+1)
    int arow = wm + (sub & 1) * 8 + rr;
    int au   = sub >> 1;
    // B: matrices (n0..7,u0),(n0..7,u0+1),(n8..15,u0),(n8..15,u0+1)
    int brow = wn + (sub >> 1) * 8 + rr;
    int bu   = sub & 1;

    // ---- mainloop ----
    for (int kb = 0; kb < NKB; kb++) {
        if (kb + NSTG - 1 < NKB) {
            int p = kb + NSTG - 1;
            int s = p & (NSTG - 1);
            uint32_t sa = sb + s * (2 * STG_B);
            uint32_t sbB = sa + STG_B;
#pragma unroll
            for (int u = 0; u < 4; u++) {
                CP16(sa + swzr[u], srcA + p * 64 + u * 16);
                CP16(sbB + swzr[u], srcB + p * 64 + u * 16);
            }
        }
        CP_COMMIT();
        CP_WAIT3();
        __syncthreads();

        uint32_t Abase = sb + (kb & (NSTG - 1)) * (2 * STG_B);
        uint32_t Bbase = Abase + STG_B;

#pragma unroll
        for (int ks = 0; ks < 2; ks++) {
            uint32_t afr[4][4];
            uint32_t bfr[8][2];
#pragma unroll
            for (int mf = 0; mf < 4; mf++) {
                int rowm = arow + mf * 16;
                LDSM4(afr[mf][0], afr[mf][1], afr[mf][2], afr[mf][3],
                      Abase + swz(rowm, ks * 2 + au));
            }
#pragma unroll
            for (int bf = 0; bf < 4; bf++) {
                int rown = brow + bf * 16;
                LDSM4(bfr[bf * 2][0], bfr[bf * 2][1], bfr[bf * 2 + 1][0], bfr[bf * 2 + 1][1],
                      Bbase + swz(rown, ks * 2 + bu));
            }
#pragma unroll
            for (int mf = 0; mf < 4; mf++)
#pragma unroll
                for (int nf = 0; nf < 8; nf++)
                    mma16(accum[mf][nf], afr[mf], bfr[nf]);
        }
        __syncthreads();
    }

    // ---- epilogue: add bias, scatter rows back ----
    int colbase = ntile * BN + wn;
#pragma unroll
    for (int mf = 0; mf < 4; mf++) {
        int row0 = wm + mf * 16 + (lane >> 2);
        int row1 = row0 + 8;
        int g0 = g_rows[base + (row0 < cnt ? row0 : 0)];
        int g1 = g_rows[base + (row1 < cnt ? row1 : 0)];
        float* o0 = out + (size_t)g0 * DOUT;
        float* o1 = out + (size_t)g1 * DOUT;
        bool v0 = row0 < cnt, v1 = row1 < cnt;
#pragma unroll
        for (int nf = 0; nf < 8; nf++) {
            int col = colbase + nf * 8 + (lane & 3) * 2;
            float2 bb = __ldg((const float2*)(bias + col));
            if (v0) {
                float2 w0;
                w0.x = accum[mf][nf][0] + bb.x;
                w0.y = accum[mf][nf][1] + bb.y;
                *(float2*)(o0 + col) = w0;
            }
            if (v1) {
                float2 w1;
                w1.x = accum[mf][nf][2] + bb.x;
                w1.y = accum[mf][nf][3] + bb.y;
                *(float2*)(o1 + col) = w1;
            }
        }
    }
}

// =================================================================
// kernel_launch
// =================================================================
extern "C" void kernel_launch(void* const* d_in, const int* in_sizes, int n_in,
                              void* d_out, int out_size) {
    const float* x     = (const float*)d_in[0];
    const void*  val   = d_in[1];
    const float* W     = (const float*)d_in[2];
    const float* gates = (const float*)d_in[3];
    const float* attn  = (const float*)d_in[4];
    const float* bias  = (const float*)d_in[5];
    float*       out   = (float*)d_out;

    cudaFuncSetAttribute(padic_gemm, cudaFuncAttributeMaxDynamicSharedMemorySize, SMEM_BYTES);

    k_detect<<<1, 32>>>((const unsigned long long*)val);
    k_zero<<<1, 32>>>();
    k_hist<<<128, 256>>>(val);
    k_scan<<<1, 32>>>();
    k_scatter<<<128, 256>>>(val);
    k_fold<<<256, 256>>>(W, gates, attn);
    k_xcvt<<<B_SZ, 128>>>(x);
    padic_gemm<<<dim3(MAX_MT, NT), 128, SMEM_BYTES>>>(bias, out);
}

// round 4
// speedup vs baseline: 1.6326x; 1.0160x over previous
#include <cuda_runtime.h>
#include <cuda_fp16.h>
#include <cstdint>

// ---------------- problem constants ----------------
#define B_SZ   32768
#define DIN    512
#define DOUT   512
#define NLEV   10

// ---------------- GEMM tiling ----------------
#define BM     128
#define BN     128
#define BK     32                  // k per stage (fp16) = 64 B per row
#define NKB    (DIN / BK)          // 16 K-blocks
#define NSTG   4                   // cp.async pipeline depth
#define MAX_MT 266                 // sum ceil(count_l/128) <= 256 + 9
#define NT     (DOUT / BN)         // 4 N-tiles
#define STG_B  (BM * 64)           // 8192 B per operand per stage
#define SMEM_BYTES (NSTG * 2 * STG_B)   // 65536

// ---------------- device scratch ----------------
__device__ int g_counts[NLEV];
__device__ int g_offsets[NLEV];
__device__ int g_cursor[NLEV];
__device__ int g_rows[B_SZ];
__device__ int g_is64;
// folded per-level matrices in fp16, [level][n][k]
__device__ __align__(16) __half g_M16[NLEV * DOUT * DIN];
// x pre-gathered into sorted order, fp16, [sorted_row][k]
__device__ __align__(16) __half g_X16[(size_t)B_SZ * DIN];

// ---------------- PTX helpers (all plain sm_80+/75+, no "a"-gated) --------
__device__ __forceinline__ uint32_t smem_u32(const void* p) {
    uint32_t a;
    asm("{ .reg .u64 t; cvta.to.shared.u64 t, %1; cvt.u32.u64 %0, t; }" : "=r"(a) : "l"(p));
    return a;
}
#define CP16(dst, src) \
    asm volatile("cp.async.cg.shared.global [%0], [%1], 16;" :: "r"(dst), "l"(src))
#define CP_COMMIT() asm volatile("cp.async.commit_group;" ::: "memory")
#define CP_WAIT2()  asm volatile("cp.async.wait_group 2;" ::: "memory")

#define LDSM4(r0, r1, r2, r3, addr) \
    asm volatile("ldmatrix.sync.aligned.m8n8.x4.shared.b16 {%0,%1,%2,%3}, [%4];" \
        : "=r"(r0), "=r"(r1), "=r"(r2), "=r"(r3) : "r"(addr))

__device__ __forceinline__ void mma16(float* d, const uint32_t* a, const uint32_t* b) {
    asm volatile(
        "mma.sync.aligned.m16n8k16.row.col.f32.f16.f16.f32 "
        "{%0,%1,%2,%3}, {%4,%5,%6,%7}, {%8,%9}, {%0,%1,%2,%3};"
        : "+f"(d[0]), "+f"(d[1]), "+f"(d[2]), "+f"(d[3])
        : "r"(a[0]), "r"(a[1]), "r"(a[2]), "r"(a[3]), "r"(b[0]), "r"(b[1]));
}

// swizzled byte offset of 16B unit u (0..3) within 64B row `row`
__device__ __forceinline__ uint32_t swz(int row, int u) {
    return (uint32_t)row * 64u + (uint32_t)((u ^ ((row >> 1) & 3)) << 4);
}

// =================================================================
// Kernel 0: detect int64 vs int32 valuations AND zero the histogram.
// =================================================================
__global__ void k_detect(const unsigned long long* __restrict__ v) {
    int t = threadIdx.x;
    if (t < NLEV) g_counts[t] = 0;
    if (t == 0) {
        int ok = 1;
        for (int i = 0; i < 256; i++)
            if (v[i] >= 10ULL) { ok = 0; break; }
        g_is64 = ok;
    }
}
__device__ __forceinline__ int load_val(const void* val, int b) {
    int v = g_is64 ? (int)((const long long*)val)[b] : ((const int*)val)[b];
    return v < 0 ? 0 : (v > 9 ? 9 : v);
}

// =================================================================
// Kernel 1: fold 10 levels into M[v] = sum_l C[v,l] * W[l], fp16 out
// =================================================================
__global__ void k_fold(const float* __restrict__ W, const float* __restrict__ gates,
                       const float* __restrict__ attn) {
    __shared__ float sC[NLEV][NLEV];
    int tid = threadIdx.x;
    if (tid < NLEV) {
        int v = tid;
        float m = -1e30f;
        for (int l = 0; l < NLEV; l++) m = fmaxf(m, attn[v * NLEV + l]);
        float e[NLEV]; float ssum = 0.f;
        for (int l = 0; l < NLEV; l++) { e[l] = expf(attn[v * NLEV + l] - m); ssum += e[l]; }
        float inv = 1.f / ssum;
        float gv = 1.f / (1.f + expf(-gates[v]));
        for (int l = 0; l < NLEV; l++) {
            float gl = 1.f / (1.f + expf(-gates[l]));
            sC[v][l] = 0.3f * e[l] * inv * gl + ((l == v) ? 0.7f * gv : 0.f);
        }
    }
    __syncthreads();

    int p  = blockIdx.x * blockDim.x + tid;   // 0 .. 65535
    int n  = p >> 7;                          // output feature 0..511
    int k4 = p & 127;                         // float4 index along K

    float4 w[NLEV];
#pragma unroll
    for (int l = 0; l < NLEV; l++)
        w[l] = __ldg((const float4*)(W + ((size_t)l * DOUT + n) * DIN) + k4);

#pragma unroll
    for (int v = 0; v < NLEV; v++) {
        float4 a = make_float4(0.f, 0.f, 0.f, 0.f);
#pragma unroll
        for (int l = 0; l < NLEV; l++) {
            float cc = sC[v][l];
            a.x += cc * w[l].x; a.y += cc * w[l].y;
            a.z += cc * w[l].z; a.w += cc * w[l].w;
        }
        __half2 h0 = __floats2half2_rn(a.x, a.y);
        __half2 h1 = __floats2half2_rn(a.z, a.w);
        uint2 o;
        o.x = *reinterpret_cast<unsigned*>(&h0);
        o.y = *reinterpret_cast<unsigned*>(&h1);
        *(uint2*)(g_M16 + ((size_t)v * DOUT + n) * DIN + (size_t)k4 * 4) = o;
    }
}

// =================================================================
// Kernels 2-4: counting sort of valuations
// =================================================================
__global__ void k_hist(const void* __restrict__ val) {
    __shared__ int sc[NLEV];
    int tid = threadIdx.x;
    if (tid < NLEV) sc[tid] = 0;
    __syncthreads();
    int b = blockIdx.x * 512 + tid;
    atomicAdd(&sc[load_val(val, b)], 1);
    __syncthreads();
    if (tid < NLEV) atomicAdd(&g_counts[tid], sc[tid]);
}
__global__ void k_scan() {
    if (threadIdx.x == 0) {
        int a = 0;
        for (int l = 0; l < NLEV; l++) { g_offsets[l] = a; g_cursor[l] = a; a += g_counts[l]; }
    }
}
__global__ void k_scatter(const void* __restrict__ val) {
    __shared__ int sc[NLEV];
    __shared__ int sbase[NLEV];
    int tid = threadIdx.x;
    if (tid < NLEV) sc[tid] = 0;
    __syncthreads();
    int b = blockIdx.x * 512 + tid;
    int v = load_val(val, b);
    int rank = atomicAdd(&sc[v], 1);
    __syncthreads();
    if (tid < NLEV) sbase[tid] = atomicAdd(&g_cursor[tid], sc[tid]);
    __syncthreads();
    g_rows[sbase[v] + rank] = b;
}

// =================================================================
// Kernel 5: convert x to fp16 AND pre-gather into sorted row order.
// =================================================================
__global__ void k_xcvt(const float* __restrict__ x) {
    int row = blockIdx.x * 2 + (threadIdx.x >> 7);
    int t = threadIdx.x & 127;
    int src = g_rows[row];
    float4 v = __ldg((const float4*)(x + (size_t)src * DIN) + t);
    __half2 h0 = __floats2half2_rn(v.x, v.y);
    __half2 h1 = __floats2half2_rn(v.z, v.w);
    uint2 o;
    o.x = *reinterpret_cast<unsigned*>(&h0);
    o.y = *reinterpret_cast<unsigned*>(&h1);
    ((uint2*)(g_X16 + (size_t)row * DIN))[t] = o;
}

// =================================================================
// Kernel 6: fp16 GEMM  out[g_rows[r]] = M16[level] @ X16[r] + bias
//   CTA 128x128, 4 warps of 64x64, mma.m16n8k16, ldmatrix fragments,
//   4-stage cp.async pipeline, single-barrier mainloop.
// =================================================================
__global__ void __launch_bounds__(128, 2) padic_gemm(
    const float* __restrict__ bias, float* __restrict__ out) {
    // ---- tile map ----
    int mt = blockIdx.x, ntile = blockIdx.y;
    int level = -1, tj = 0, acc = 0;
#pragma unroll
    for (int l = 0; l < NLEV; l++) {
        int c = g_counts[l];
        int tl = (c + BM - 1) >> 7;
        if (level < 0 && mt < acc + tl) { level = l; tj = mt - acc; }
        acc += tl;
    }
    if (level < 0) return;
    int base = g_offsets[level] + tj * BM;
    int cnt  = g_counts[level] - tj * BM;
    if (cnt > BM) cnt = BM;

    extern __shared__ char smem[];
    uint32_t sb = smem_u32(smem);
    int tid = threadIdx.x, lane = tid & 31, wid = tid >> 5;
    int wm = (wid & 1) * 64;
    int wn = (wid >> 1) * 64;

    // producer: thread r fills A row r and B row r of each stage (4 x 16B each)
    int r = tid;
    int rowA = base + r; if (rowA > B_SZ - 1) rowA = B_SZ - 1;
    const char* srcA = (const char*)(g_X16 + (size_t)rowA * DIN);
    const char* srcB = (const char*)(g_M16 + ((size_t)level * DOUT + (size_t)(ntile * BN + r)) * DIN);
    uint32_t swzr[4];
#pragma unroll
    for (int u = 0; u < 4; u++) swzr[u] = swz(r, u);

    float accum[4][8][4];
#pragma unroll
    for (int mf = 0; mf < 4; mf++)
#pragma unroll
        for (int nf = 0; nf < 8; nf++)
#pragma unroll
            for (int q = 0; q < 4; q++) accum[mf][nf][q] = 0.f;

    // ---- prologue: stages 0..2 ----
#pragma unroll
    for (int p = 0; p < NSTG - 1; p++) {
        uint32_t sa = sb + p * (2 * STG_B);
        uint32_t sbB = sa + STG_B;
#pragma unroll
        for (int u = 0; u < 4; u++) {
            CP16(sa + swzr[u], srcA + p * 64 + u * 16);
            CP16(sbB + swzr[u], srcB + p * 64 + u * 16);
        }
        CP_COMMIT();
    }

    // precompute LDSM lane addresses (relative to stage base)
    int sub = lane >> 3, rr = lane & 7;
    int arow = wm + (sub & 1) * 8 + rr;
    int au   = sub >> 1;
    int brow = wn + (sub >> 1) * 8 + rr;
    int bu   = sub & 1;

    // ---- mainloop: wait(stage kb) ; barrier ; prefetch(kb+3) ; compute(kb) ----
    for (int kb = 0; kb < NKB; kb++) {
        CP_WAIT2();
        __syncthreads();

        if (kb + NSTG - 1 < NKB) {
            int p = kb + NSTG - 1;
            int s = p & (NSTG - 1);
            uint32_t sa = sb + s * (2 * STG_B);
            uint32_t sbB = sa + STG_B;
#pragma unroll
            for (int u = 0; u < 4; u++) {
                CP16(sa + swzr[u], srcA + p * 64 + u * 16);
                CP16(sbB + swzr[u], srcB + p * 64 + u * 16);
            }
        }
        CP_COMMIT();

        uint32_t Abase = sb + (kb & (NSTG - 1)) * (2 * STG_B);
        uint32_t Bbase = Abase + STG_B;

#pragma unroll
        for (int ks = 0; ks < 2; ks++) {
            uint32_t afr[4][4];
            uint32_t bfr[8][2];
#pragma unroll
            for (int mf = 0; mf < 4; mf++) {
                int rowm = arow + mf * 16;
                LDSM4(afr[mf][0], afr[mf][1], afr[mf][2], afr[mf][3],
                      Abase + swz(rowm, ks * 2 + au));
            }
#pragma unroll
            for (int bf = 0; bf < 4; bf++) {
                int rown = brow + bf * 16;
                LDSM4(bfr[bf * 2][0], bfr[bf * 2][1], bfr[bf * 2 + 1][0], bfr[bf * 2 + 1][1],
                      Bbase + swz(rown, ks * 2 + bu));
            }
#pragma unroll
            for (int mf = 0; mf < 4; mf++)
#pragma unroll
                for (int nf = 0; nf < 8; nf++)
                    mma16(accum[mf][nf], afr[mf], bfr[nf]);
        }
    }

    // ---- epilogue: add bias, scatter rows back ----
    int colbase = ntile * BN + wn;
    float2 bb[8];
#pragma unroll
    for (int nf = 0; nf < 8; nf++)
        bb[nf] = __ldg((const float2*)(bias + colbase + nf * 8 + (lane & 3) * 2));
#pragma unroll
    for (int mf = 0; mf < 4; mf++) {
        int row0 = wm + mf * 16 + (lane >> 2);
        int row1 = row0 + 8;
        int g0 = g_rows[base + (row0 < cnt ? row0 : 0)];
        int g1 = g_rows[base + (row1 < cnt ? row1 : 0)];
        float* o0 = out + (size_t)g0 * DOUT;
        float* o1 = out + (size_t)g1 * DOUT;
        bool v0 = row0 < cnt, v1 = row1 < cnt;
#pragma unroll
        for (int nf = 0; nf < 8; nf++) {
            int col = colbase + nf * 8 + (lane & 3) * 2;
            if (v0) {
                float2 w0;
                w0.x = accum[mf][nf][0] + bb[nf].x;
                w0.y = accum[mf][nf][1] + bb[nf].y;
                *(float2*)(o0 + col) = w0;
            }
            if (v1) {
                float2 w1;
                w1.x = accum[mf][nf][2] + bb[nf].x;
                w1.y = accum[mf][nf][3] + bb[nf].y;
                *(float2*)(o1 + col) = w1;
            }
        }
    }
}

// =================================================================
// kernel_launch
// =================================================================
extern "C" void kernel_launch(void* const* d_in, const int* in_sizes, int n_in,
                              void* d_out, int out_size) {
    const float* x     = (const float*)d_in[0];
    const void*  val   = d_in[1];
    const float* W     = (const float*)d_in[2];
    const float* gates = (const float*)d_in[3];
    const float* attn  = (const float*)d_in[4];
    const float* bias  = (const float*)d_in[5];
    float*       out   = (float*)d_out;

    cudaFuncSetAttribute(padic_gemm, cudaFuncAttributeMaxDynamicSharedMemorySize, SMEM_BYTES);

    k_detect<<<1, 32>>>((const unsigned long long*)val);
    k_hist<<<64, 512>>>(val);
    k_scan<<<1, 32>>>();
    k_scatter<<<64, 512>>>(val);
    k_fold<<<256, 256>>>(W, gates, attn);
    k_xcvt<<<B_SZ / 2, 256>>>(x);
    padic_gemm<<<dim3(MAX_MT, NT), 128, SMEM_BYTES>>>(bias, out);
}